// round 6
// baseline (speedup 1.0000x reference)
#include <cuda_runtime.h>
#include <math.h>

// Problem constants (fixed by reference: x = (4, 64, 128, 128) fp32)
#define HH 128
#define WW 128
#define BB 4

// Scratch (allocation-free: __device__ globals)
__device__ float g_A[BB * 128 * HH * WW];   // 32 MB ping
__device__ float g_B[BB * 128 * HH * WW];   // 32 MB pong
__device__ float g_off[BB * 18 * HH * WW];  // offsets
__device__ float g_wtc[128 * 9 * 128];      // transposed conv weights  [cin*9][OP]
__device__ float g_wto[128 * 9 * 24];       // transposed offset-conv weights (pad 24)
__device__ float g_wtd[128 * 9 * 256];      // transposed+DUPLICATED deform weights
                                            // [c*9+k][2*O]: {w,w} pairs per oc

typedef unsigned long long u64;

// Packed fp32x2 ops (Blackwell FFMA2 — only reachable via PTX)
#define FMA2(d, a, b, c) \
    asm("fma.rn.f32x2 %0, %1, %2, %3;" : "=l"(d) : "l"(a), "l"(b), "l"(c))
#define PACKDUP(out, f) \
    asm("mov.b64 %0, {%1, %1};" : "=l"(out) : "r"(__float_as_uint(f)))
#define UNPACK2(lo, hi, in) \
    asm("mov.b64 {%0, %1}, %2;" : "=r"(lo), "=r"(hi) : "l"(in))

// cp.async (LDGSTS)
#define CP_ASYNC4(dst_s, src_g, szr) \
    asm volatile("cp.async.ca.shared.global [%0], [%1], 4, %2;" \
                 :: "r"(dst_s), "l"(src_g), "r"(szr))
#define CP_ASYNC16(dst_s, src_g) \
    asm volatile("cp.async.ca.shared.global [%0], [%1], 16;" \
                 :: "r"(dst_s), "l"(src_g))
#define CP_COMMIT() asm volatile("cp.async.commit_group;")
#define CP_WAIT0()  asm volatile("cp.async.wait_group 0;")

__device__ __forceinline__ unsigned s2u(const void* p) {
    return (unsigned)__cvta_generic_to_shared(p);
}
__device__ __forceinline__ float lrelu(float v) { return v >= 0.f ? v : 0.2f * v; }

// ---------------------------------------------------------------------------
// Weight transpose + pad: wt[j*OP + o] = (o < O) ? w[o*C9 + j] : 0
// ---------------------------------------------------------------------------
__global__ void wt_pad_kernel(const float* __restrict__ w, float* __restrict__ wt,
                              int C9, int O, int OP)
{
    int idx = blockIdx.x * 256 + threadIdx.x;
    if (idx < C9 * OP) {
        int j = idx / OP;
        int o = idx - j * OP;
        wt[idx] = (o < O) ? w[o * C9 + j] : 0.f;
    }
}

// Transpose + duplicate: wt2[j][2o] = wt2[j][2o+1] = w[o][j]
__global__ void wt_dup_kernel(const float* __restrict__ w, float* __restrict__ wt2,
                              int C9, int O)
{
    int idx = blockIdx.x * 256 + threadIdx.x;
    if (idx < C9 * O) {
        int o = idx / C9;
        int j = idx - o * C9;
        float v = w[idx];
        wt2[j * 2 * O + 2 * o]     = v;
        wt2[j * 2 * O + 2 * o + 1] = v;
    }
}

// ---------------------------------------------------------------------------
// Plain 3x3 conv, stride 1, pad 1, optional LeakyReLU.
// 32(x) x 16(y) px tile, OCB oc per block, 128 threads.
// Thread: 4 px x OCB oc as OCB/2 f32x2 pairs.
// cp.async double-buffered input halo + weight slab, 1 barrier per chunk.
// in_s rows padded to 36 floats -> rowv is LDS.128 + LDS.64.
// ---------------------------------------------------------------------------
template<int CIN, int OCB, bool RELU>
__global__ __launch_bounds__(128)
void conv3x3_kernel(const float* __restrict__ x, const float* __restrict__ wt,
                    const float* __restrict__ bias, float* __restrict__ y,
                    int Cout, int OP, int n_ocb)
{
    __shared__ float w_s[2][36][OCB];
    __shared__ float in_s[2][4][18][36];   // row padded to 36 (16B-aligned rows)

    const int t   = threadIdx.x;
    const int lx  = t & 7;
    const int ly  = t >> 3;
    const int bx  = blockIdx.x * 32;
    const int by  = blockIdx.y * 16;
    const int b   = blockIdx.z / n_ocb;
    const int ocb = blockIdx.z % n_ocb;
    const int oc0 = ocb * OCB;

    const float* xb = x + b * CIN * HH * WW;

    u64 acc[OCB / 2][4];
    #pragma unroll
    for (int q = 0; q < OCB / 2; q++)
        #pragma unroll
        for (int p = 0; p < 4; p++) acc[q][p] = 0ull;

    // async chunk loader: 4 input channels + weight slab into buffer bi
    auto load_chunk = [&](int c0, int bi) {
        const float* xc = xb + c0 * HH * WW;
        for (int i = t; i < 4 * 18 * 34; i += 128) {
            int cc  = i / (18 * 34);
            int rem = i - cc * (18 * 34);
            int r   = rem / 34;
            int col = rem - r * 34;
            int gy  = by - 1 + r;
            int gx  = bx - 1 + col;
            bool ok = ((unsigned)gy < (unsigned)HH) & ((unsigned)gx < (unsigned)WW);
            const float* src = xc + cc * HH * WW + (ok ? gy * WW + gx : 0);
            int sz = ok ? 4 : 0;
            CP_ASYNC4(s2u(&in_s[bi][cc][r][col]), src, sz);
        }
        for (int i = t; i < 36 * (OCB / 4); i += 128) {
            int row = i / (OCB / 4);
            int q   = i - row * (OCB / 4);
            CP_ASYNC16(s2u(&w_s[bi][row][q * 4]),
                       &wt[(c0 * 9 + row) * OP + oc0 + q * 4]);
        }
    };

    load_chunk(0, 0);
    CP_COMMIT();

    int buf = 0;
    for (int c0 = 0; c0 < CIN; c0 += 4) {
        CP_WAIT0();
        __syncthreads();
        if (c0 + 4 < CIN) { load_chunk(c0 + 4, buf ^ 1); CP_COMMIT(); }

        #pragma unroll
        for (int cc = 0; cc < 4; cc++) {
            #pragma unroll
            for (int ry = 0; ry < 3; ry++) {
                float4 ra = *(const float4*)&in_s[buf][cc][ly + ry][lx * 4];
                float2 rb = *(const float2*)&in_s[buf][cc][ly + ry][lx * 4 + 4];
                float rowv[6] = {ra.x, ra.y, ra.z, ra.w, rb.x, rb.y};
                #pragma unroll
                for (int rx = 0; rx < 3; rx++) {
                    u64 iv2[4];
                    #pragma unroll
                    for (int p = 0; p < 4; p++) PACKDUP(iv2[p], rowv[p + rx]);
                    const u64* wp = (const u64*)&w_s[buf][cc * 9 + ry * 3 + rx][0];
                    #pragma unroll
                    for (int q = 0; q < OCB / 2; q++) {
                        u64 w2 = wp[q];
                        #pragma unroll
                        for (int p = 0; p < 4; p++)
                            FMA2(acc[q][p], w2, iv2[p], acc[q][p]);
                    }
                }
            }
        }
        buf ^= 1;
    }

    const int gy = by + ly;
    const int gx = bx + lx * 4;
    #pragma unroll
    for (int q = 0; q < OCB / 2; q++) {
        float lo[4], hi[4];
        #pragma unroll
        for (int p = 0; p < 4; p++) {
            unsigned int ul, uh;
            UNPACK2(ul, uh, acc[q][p]);
            lo[p] = __uint_as_float(ul);
            hi[p] = __uint_as_float(uh);
        }
        #pragma unroll
        for (int h = 0; h < 2; h++) {
            int oc = 2 * q + h;
            if (oc0 + oc < Cout) {
                float bvv = bias[oc0 + oc];
                const float* s = h ? hi : lo;
                float v0 = s[0] + bvv, v1 = s[1] + bvv;
                float v2 = s[2] + bvv, v3 = s[3] + bvv;
                if (RELU) { v0 = lrelu(v0); v1 = lrelu(v1); v2 = lrelu(v2); v3 = lrelu(v3); }
                *(float4*)&y[((b * Cout + oc0 + oc) * HH + gy) * WW + gx] =
                    make_float4(v0, v1, v2, v3);
            }
        }
    }
}

// ---------------------------------------------------------------------------
// Deformable 3x3 conv + LeakyReLU.
// 256 threads = 16 og x 16 pg; 64 px on one row, all O channels.
// acc = pixel-pairs (u64): val px-pairs load directly from smem (no packs);
// weights are pre-duplicated {w,w} in gmem, read via LDG.128 (L2-broadcast,
// no smem). smem = taps + double-buffered val only (27.6KB) -> 4 CTAs/SM.
// Per k-step: 1 LDS.128 + OT/2 LDG.128 + 2*OT FMA2 (~76% FMA2 slots).
// ---------------------------------------------------------------------------
template<int C, int O>
__global__ __launch_bounds__(256)
void dconv3x3_kernel(const float* __restrict__ x, const float* __restrict__ off,
                     const float* __restrict__ wt2, const float* __restrict__ bias,
                     float* __restrict__ y)
{
    constexpr int CC = 4;
    constexpr int PX = 64;
    constexpr int KS = CC * 9;          // 36
    constexpr int NC = C / CC;
    constexpr int OT = O / 16;          // 8 (O=128) or 4 (O=64)
    constexpr int HS = HH * WW;

    __shared__ float t_wy[9 * PX];
    __shared__ float t_wx[9 * PX];
    __shared__ int   t_y0[9 * PX];
    __shared__ int   t_x0[9 * PX];
    __shared__ float val_s[2][KS * PX];

    const int t  = threadIdx.x;
    const int og = t >> 4;               // 0..15
    const int pg = t & 15;               // 0..15 (px base = pg*4)
    const int x0 = blockIdx.x * PX;
    const int yy = blockIdx.y;
    const int b  = blockIdx.z;

    // Phase 0: taps (px innermost -> coalesced offset reads)
    for (int j = t; j < 9 * PX; j += 256) {
        int px = j & (PX - 1);
        int k  = j >> 6;
        int gx = x0 + px;
        float dy = off[((b * 18 + 2 * k) * HH + yy) * WW + gx];
        float dx = off[((b * 18 + 2 * k + 1) * HH + yy) * WW + gx];
        int ky = k / 3;
        int kx = k - ky * 3;
        float py  = (float)(yy + ky - 1) + dy;
        float pxx = (float)(gx + kx - 1) + dx;
        float fy = floorf(py), fx = floorf(pxx);
        t_y0[j] = (int)fy;
        t_x0[j] = (int)fx;
        t_wy[j] = py - fy;
        t_wx[j] = pxx - fx;
    }

    const float* xb = x + b * C * HS;

    // phase A: one thread owns one (k,px) for all CC channels -> address calc
    // once, 16 LDGs batched (high MLP), 4 STS.
    auto phaseA = [&](int ci, int bi) {
        float* dst = val_s[bi];
        const float* xc = xb + ci * CC * HS;
        for (int j = t; j < 9 * PX; j += 256) {
            int yi = t_y0[j], xi = t_x0[j];
            float wyv = t_wy[j], wxv = t_wx[j];
            bool y0in = (unsigned)yi < (unsigned)HH;
            bool y1in = (unsigned)(yi + 1) < (unsigned)HH;
            bool x0in = (unsigned)xi < (unsigned)WW;
            bool x1in = (unsigned)(xi + 1) < (unsigned)WW;
            bool ok00 = y0in & x0in, ok01 = y0in & x1in;
            bool ok10 = y1in & x0in, ok11 = y1in & x1in;
            int base = yi * WW + xi;
            float a00[CC], a01[CC], a10[CC], a11[CC];
            #pragma unroll
            for (int cc = 0; cc < CC; cc++) {
                const float* p = xc + cc * HS + base;
                a00[cc] = ok00 ? p[0]      : 0.f;
                a01[cc] = ok01 ? p[1]      : 0.f;
                a10[cc] = ok10 ? p[WW]     : 0.f;
                a11[cc] = ok11 ? p[WW + 1] : 0.f;
            }
            int k  = j >> 6;
            int px = j & (PX - 1);
            #pragma unroll
            for (int cc = 0; cc < CC; cc++) {
                float v0 = a00[cc] + (a01[cc] - a00[cc]) * wxv;
                float v1 = a10[cc] + (a11[cc] - a10[cc]) * wxv;
                dst[(cc * 9 + k) * PX + px] = v0 + (v1 - v0) * wyv;
            }
        }
    };

    u64 acc[OT][2];     // [oc][px-pair]
    #pragma unroll
    for (int q = 0; q < OT; q++) { acc[q][0] = 0ull; acc[q][1] = 0ull; }

    __syncthreads();          // taps visible
    phaseA(0, 0);

    const float* wog = wt2 + og * (2 * OT);   // this thread's oc-group column

    for (int i = 0; i < NC; i++) {
        __syncthreads();      // val(i) ready; val(i-1) consumers done
        const float* vb = val_s[i & 1];
        const float* wrow = wog + (i * KS) * (2 * O);
        #pragma unroll 4
        for (int kk = 0; kk < KS; kk++) {
            const u64* vp = (const u64*)&vb[kk * PX + pg * 4];
            u64 v01 = vp[0], v23 = vp[1];
            const ulonglong2* wp2 = (const ulonglong2*)(wrow + kk * 2 * O);
            #pragma unroll
            for (int q2 = 0; q2 < OT / 2; q2++) {
                ulonglong2 ww = wp2[q2];
                FMA2(acc[2 * q2][0],     ww.x, v01, acc[2 * q2][0]);
                FMA2(acc[2 * q2][1],     ww.x, v23, acc[2 * q2][1]);
                FMA2(acc[2 * q2 + 1][0], ww.y, v01, acc[2 * q2 + 1][0]);
                FMA2(acc[2 * q2 + 1][1], ww.y, v23, acc[2 * q2 + 1][1]);
            }
        }
        if (i + 1 < NC) phaseA(i + 1, (i + 1) & 1);
    }

    const int gx = x0 + pg * 4;
    #pragma unroll
    for (int q = 0; q < OT; q++) {
        int o = og * OT + q;
        float bvv = bias[o];
        unsigned int u0, u1, u2, u3;
        UNPACK2(u0, u1, acc[q][0]);
        UNPACK2(u2, u3, acc[q][1]);
        float4 r4;
        r4.x = lrelu(__uint_as_float(u0) + bvv);
        r4.y = lrelu(__uint_as_float(u1) + bvv);
        r4.z = lrelu(__uint_as_float(u2) + bvv);
        r4.w = lrelu(__uint_as_float(u3) + bvv);
        *(float4*)&y[((b * O + o) * HH + yy) * WW + gx] = r4;
    }
}

// ---------------------------------------------------------------------------
// Launch: 3 stages of conv(+leaky) -> offset conv -> deform conv(+leaky),
// each preceded by its weight transposes. Default stream, graph-capturable.
// ---------------------------------------------------------------------------
extern "C" void kernel_launch(void* const* d_in, const int* in_sizes, int n_in,
                              void* d_out, int out_size)
{
    const float* x = (const float*)d_in[0];
    const float* p[18];
    for (int i = 0; i < 18; i++) p[i] = (const float*)d_in[1 + i];

    float *A, *Bf, *OFF, *WTC, *WTO, *WTD;
    cudaGetSymbolAddress((void**)&A,   g_A);
    cudaGetSymbolAddress((void**)&Bf,  g_B);
    cudaGetSymbolAddress((void**)&OFF, g_off);
    cudaGetSymbolAddress((void**)&WTC, g_wtc);
    cudaGetSymbolAddress((void**)&WTO, g_wto);
    cudaGetSymbolAddress((void**)&WTD, g_wtd);

    dim3 blk128(128), blk256(256);
    dim3 dgrid(WW / 64, HH, BB);

    #define WTP(src, dst, C9, O, OP) \
        wt_pad_kernel<<<((C9) * (OP) + 255) / 256, 256>>>(src, dst, C9, O, OP)
    #define WTD2(src, C9, O) \
        wt_dup_kernel<<<((C9) * (O) + 255) / 256, 256>>>(src, WTD, C9, O)

    // ---- stage 1: 64 -> 128 ----
    WTP(p[0], WTC, 64 * 9, 128, 128);
    WTP(p[2], WTO, 128 * 9, 18, 24);
    WTD2(p[4], 128 * 9, 128);
    conv3x3_kernel<64, 16, true><<<dim3(4, 8, BB * 8), blk128>>>(x, WTC, p[1], A, 128, 128, 8);
    conv3x3_kernel<128, 8, false><<<dim3(4, 8, BB * 3), blk128>>>(A, WTO, p[3], OFF, 18, 24, 3);
    dconv3x3_kernel<128, 128><<<dgrid, blk256>>>(A, OFF, WTD, p[5], Bf);

    // ---- stage 2: 128 -> 128 ----
    WTP(p[6], WTC, 128 * 9, 128, 128);
    WTP(p[8], WTO, 128 * 9, 18, 24);
    WTD2(p[10], 128 * 9, 128);
    conv3x3_kernel<128, 16, true><<<dim3(4, 8, BB * 8), blk128>>>(Bf, WTC, p[7], A, 128, 128, 8);
    conv3x3_kernel<128, 8, false><<<dim3(4, 8, BB * 3), blk128>>>(A, WTO, p[9], OFF, 18, 24, 3);
    dconv3x3_kernel<128, 128><<<dgrid, blk256>>>(A, OFF, WTD, p[11], Bf);

    // ---- stage 3: 128 -> 64 ----
    WTP(p[12], WTC, 128 * 9, 64, 64);
    WTP(p[14], WTO, 64 * 9, 18, 24);
    WTD2(p[16], 64 * 9, 64);
    conv3x3_kernel<128, 16, true><<<dim3(4, 8, BB * 4), blk128>>>(Bf, WTC, p[13], A, 64, 64, 4);
    conv3x3_kernel<64, 8, false><<<dim3(4, 8, BB * 3), blk128>>>(A, WTO, p[15], OFF, 18, 24, 3);
    dconv3x3_kernel<64, 64><<<dgrid, blk256>>>(A, OFF, WTD, p[17], (float*)d_out);

    #undef WTP
    #undef WTD2
}

// round 7
// speedup vs baseline: 1.4350x; 1.4350x over previous
#include <cuda_runtime.h>
#include <math.h>

// Problem constants (fixed by reference: x = (4, 64, 128, 128) fp32)
#define HH 128
#define WW 128
#define BB 4

// Scratch (allocation-free: __device__ globals)
__device__ float g_A[BB * 128 * HH * WW];        // 32 MB ping
__device__ float g_B[BB * 128 * HH * WW];        // 32 MB pong
__device__ float g_off[BB * 18 * HH * WW];       // offsets
__device__ float g_wtc[3][128 * 9 * 128];        // per-stage transposed conv weights
__device__ float g_wto[3][128 * 9 * 24];         // per-stage transposed offset weights
__device__ float g_wtd[3][128 * 9 * 128];        // per-stage transposed deform weights

typedef unsigned long long u64;

// Packed fp32x2 ops (Blackwell FFMA2 — only reachable via PTX)
#define FMA2(d, a, b, c) \
    asm("fma.rn.f32x2 %0, %1, %2, %3;" : "=l"(d) : "l"(a), "l"(b), "l"(c))
#define PACKDUP(out, f) \
    asm("mov.b64 %0, {%1, %1};" : "=l"(out) : "r"(__float_as_uint(f)))
#define UNPACK2(lo, hi, in) \
    asm("mov.b64 {%0, %1}, %2;" : "=r"(lo), "=r"(hi) : "l"(in))

// cp.async (LDGSTS)
#define CP_ASYNC4(dst_s, src_g, szr) \
    asm volatile("cp.async.ca.shared.global [%0], [%1], 4, %2;" \
                 :: "r"(dst_s), "l"(src_g), "r"(szr))
#define CP_ASYNC16(dst_s, src_g) \
    asm volatile("cp.async.ca.shared.global [%0], [%1], 16;" \
                 :: "r"(dst_s), "l"(src_g))
#define CP_COMMIT() asm volatile("cp.async.commit_group;")
#define CP_WAIT0()  asm volatile("cp.async.wait_group 0;")

__device__ __forceinline__ unsigned s2u(const void* p) {
    return (unsigned)__cvta_generic_to_shared(p);
}
__device__ __forceinline__ float lrelu(float v) { return v >= 0.f ? v : 0.2f * v; }

// ---------------------------------------------------------------------------
// One prep kernel does ALL 9 weight transposes (they depend only on inputs).
// Job j: dst[j][row*OP + o] = (o < O) ? src[j][o*C9 + row] : 0
// ---------------------------------------------------------------------------
struct PrepJobs {
    const float* src[9];
    float*       dst[9];
    int C9[9], O[9], OP[9];
};

__global__ void prep_kernel(PrepJobs jobs)
{
    int job = blockIdx.y;
    int C9 = jobs.C9[job], O = jobs.O[job], OP = jobs.OP[job];
    int n = C9 * OP;
    const float* src = jobs.src[job];
    float* dst = jobs.dst[job];
    for (int idx = blockIdx.x * 256 + threadIdx.x; idx < n; idx += gridDim.x * 256) {
        int j = idx / OP;
        int o = idx - j * OP;
        dst[idx] = (o < O) ? src[o * C9 + j] : 0.f;
    }
}

// ---------------------------------------------------------------------------
// Plain 3x3 conv, stride 1, pad 1, optional LeakyReLU.
// 32(x) x 16(y) px tile, OCB oc per block, 128 threads.
// Thread: 4 px x OCB oc as OCB/2 f32x2 pairs.
// cp.async double-buffered input halo + weight slab, 1 barrier per chunk.
// Weight pairs read as ulonglong2 (LDS.128, 2 pairs per load).
// ---------------------------------------------------------------------------
template<int CIN, int OCB, bool RELU>
__global__ __launch_bounds__(128)
void conv3x3_kernel(const float* __restrict__ x, const float* __restrict__ wt,
                    const float* __restrict__ bias, float* __restrict__ y,
                    int Cout, int OP, int n_ocb)
{
    __shared__ __align__(16) float w_s[2][36][OCB];
    __shared__ __align__(16) float in_s[2][4][18][36];  // rows padded to 36

    const int t   = threadIdx.x;
    const int lx  = t & 7;
    const int ly  = t >> 3;
    const int bx  = blockIdx.x * 32;
    const int by  = blockIdx.y * 16;
    const int b   = blockIdx.z / n_ocb;
    const int ocb = blockIdx.z % n_ocb;
    const int oc0 = ocb * OCB;

    const float* xb = x + b * CIN * HH * WW;

    u64 acc[OCB / 2][4];
    #pragma unroll
    for (int q = 0; q < OCB / 2; q++)
        #pragma unroll
        for (int p = 0; p < 4; p++) acc[q][p] = 0ull;

    auto load_chunk = [&](int c0, int bi) {
        const float* xc = xb + c0 * HH * WW;
        for (int i = t; i < 4 * 18 * 34; i += 128) {
            int cc  = i / (18 * 34);
            int rem = i - cc * (18 * 34);
            int r   = rem / 34;
            int col = rem - r * 34;
            int gy  = by - 1 + r;
            int gx  = bx - 1 + col;
            bool ok = ((unsigned)gy < (unsigned)HH) & ((unsigned)gx < (unsigned)WW);
            const float* src = xc + cc * HH * WW + (ok ? gy * WW + gx : 0);
            int sz = ok ? 4 : 0;
            CP_ASYNC4(s2u(&in_s[bi][cc][r][col]), src, sz);
        }
        for (int i = t; i < 36 * (OCB / 4); i += 128) {
            int row = i / (OCB / 4);
            int q   = i - row * (OCB / 4);
            CP_ASYNC16(s2u(&w_s[bi][row][q * 4]),
                       &wt[(c0 * 9 + row) * OP + oc0 + q * 4]);
        }
    };

    load_chunk(0, 0);
    CP_COMMIT();

    int buf = 0;
    for (int c0 = 0; c0 < CIN; c0 += 4) {
        CP_WAIT0();
        __syncthreads();
        if (c0 + 4 < CIN) { load_chunk(c0 + 4, buf ^ 1); CP_COMMIT(); }

        #pragma unroll
        for (int cc = 0; cc < 4; cc++) {
            #pragma unroll
            for (int ry = 0; ry < 3; ry++) {
                float4 ra = *(const float4*)&in_s[buf][cc][ly + ry][lx * 4];
                float2 rb = *(const float2*)&in_s[buf][cc][ly + ry][lx * 4 + 4];
                float rowv[6] = {ra.x, ra.y, ra.z, ra.w, rb.x, rb.y};
                #pragma unroll
                for (int rx = 0; rx < 3; rx++) {
                    u64 iv2[4];
                    #pragma unroll
                    for (int p = 0; p < 4; p++) PACKDUP(iv2[p], rowv[p + rx]);
                    const ulonglong2* wp2 =
                        (const ulonglong2*)&w_s[buf][cc * 9 + ry * 3 + rx][0];
                    #pragma unroll
                    for (int q2 = 0; q2 < OCB / 4; q2++) {
                        ulonglong2 ww = wp2[q2];
                        #pragma unroll
                        for (int p = 0; p < 4; p++)
                            FMA2(acc[2 * q2][p], ww.x, iv2[p], acc[2 * q2][p]);
                        #pragma unroll
                        for (int p = 0; p < 4; p++)
                            FMA2(acc[2 * q2 + 1][p], ww.y, iv2[p], acc[2 * q2 + 1][p]);
                    }
                }
            }
        }
        buf ^= 1;
    }

    const int gy = by + ly;
    const int gx = bx + lx * 4;
    #pragma unroll
    for (int q = 0; q < OCB / 2; q++) {
        float lo[4], hi[4];
        #pragma unroll
        for (int p = 0; p < 4; p++) {
            unsigned int ul, uh;
            UNPACK2(ul, uh, acc[q][p]);
            lo[p] = __uint_as_float(ul);
            hi[p] = __uint_as_float(uh);
        }
        #pragma unroll
        for (int h = 0; h < 2; h++) {
            int oc = 2 * q + h;
            if (oc0 + oc < Cout) {
                float bvv = bias[oc0 + oc];
                const float* s = h ? hi : lo;
                float v0 = s[0] + bvv, v1 = s[1] + bvv;
                float v2 = s[2] + bvv, v3 = s[3] + bvv;
                if (RELU) { v0 = lrelu(v0); v1 = lrelu(v1); v2 = lrelu(v2); v3 = lrelu(v3); }
                *(float4*)&y[((b * Cout + oc0 + oc) * HH + gy) * WW + gx] =
                    make_float4(v0, v1, v2, v3);
            }
        }
    }
}

// ---------------------------------------------------------------------------
// Deformable 3x3 conv + LeakyReLU (R4 structure).
// 256 threads, 64 px on one row, all O channels. CC=4 chunks,
// double-buffered val + weights (cp.async), one barrier per chunk.
// Phase B: weight pairs via ulonglong2 LDS.128 (2 pairs/load).
// ---------------------------------------------------------------------------
template<int C, int O>
__global__ __launch_bounds__(256)
void dconv3x3_kernel(const float* __restrict__ x, const float* __restrict__ off,
                     const float* __restrict__ wt, const float* __restrict__ bias,
                     float* __restrict__ y)
{
    constexpr int CC = 4;
    constexpr int PX = 64;
    constexpr int KS = CC * 9;          // 36
    constexpr int NC = C / CC;
    constexpr int OT = O / 16;          // 8 (O=128) or 4 (O=64)
    extern __shared__ __align__(16) float dsm[];
    float* t_wy  = dsm;                       // 576
    float* t_wx  = dsm + 576;                 // 576
    int*   t_y0  = (int*)(dsm + 1152);        // 576
    int*   t_x0  = (int*)(dsm + 1728);        // 576
    float* val_s = dsm + 2304;                // 2 * KS * PX
    float* w_s   = dsm + 2304 + 2 * KS * PX;  // 2 * KS * O

    const int t  = threadIdx.x;
    const int og = t >> 4;               // 0..15
    const int pg = t & 15;               // 0..15 (px base = pg*4)
    const int x0 = blockIdx.x * PX;
    const int yy = blockIdx.y;
    const int b  = blockIdx.z;

    // Phase 0: taps (px innermost -> coalesced offset reads)
    for (int j = t; j < 9 * PX; j += 256) {
        int px = j & (PX - 1);
        int k  = j >> 6;
        int gx = x0 + px;
        float dy = off[((b * 18 + 2 * k) * HH + yy) * WW + gx];
        float dx = off[((b * 18 + 2 * k + 1) * HH + yy) * WW + gx];
        int ky = k / 3;
        int kx = k - ky * 3;
        float py  = (float)(yy + ky - 1) + dy;
        float pxx = (float)(gx + kx - 1) + dx;
        float fy = floorf(py), fx = floorf(pxx);
        t_y0[j] = (int)fy;
        t_x0[j] = (int)fx;
        t_wy[j] = py - fy;
        t_wx[j] = pxx - fx;
    }

    const float* xb = x + b * C * HH * WW;

    auto load_w = [&](int ci, int bi) {
        const float4* src = (const float4*)(wt + ci * KS * O);
        float* dst = w_s + bi * KS * O;
        for (int i = t; i < KS * O / 4; i += 256)
            CP_ASYNC16(s2u(dst + i * 4), src + i);
    };

    auto phaseA = [&](int ci, int bi) {
        float* dst = val_s + bi * KS * PX;
        #pragma unroll 3
        for (int j = t; j < KS * PX; j += 256) {
            int px = j & (PX - 1);
            int kj = j >> 6;             // cc*9 + k
            int cc = kj / 9;
            int k  = kj - cc * 9;
            int ti = k * PX + px;
            int yi = t_y0[ti], xi = t_x0[ti];
            float wyv = t_wy[ti], wxv = t_wx[ti];
            const float* xc = xb + (ci * CC + cc) * HH * WW;
            float a00 = 0.f, a01 = 0.f, a10 = 0.f, a11 = 0.f;
            bool xin0 = (unsigned)xi < (unsigned)WW;
            bool xin1 = (unsigned)(xi + 1) < (unsigned)WW;
            if ((unsigned)yi < (unsigned)HH) {
                const float* row = xc + yi * WW;
                if (xin0) a00 = row[xi];
                if (xin1) a01 = row[xi + 1];
            }
            if ((unsigned)(yi + 1) < (unsigned)HH) {
                const float* row = xc + (yi + 1) * WW;
                if (xin0) a10 = row[xi];
                if (xin1) a11 = row[xi + 1];
            }
            float v0 = a00 + (a01 - a00) * wxv;
            float v1 = a10 + (a11 - a10) * wxv;
            dst[j] = v0 + (v1 - v0) * wyv;
        }
    };

    u64 acc[OT / 2][4];
    #pragma unroll
    for (int q = 0; q < OT / 2; q++)
        #pragma unroll
        for (int p = 0; p < 4; p++) acc[q][p] = 0ull;

    // prologue
    __syncthreads();          // taps visible
    load_w(0, 0);
    CP_COMMIT();
    phaseA(0, 0);

    for (int i = 0; i < NC; i++) {
        CP_WAIT0();
        __syncthreads();      // val(i), w(i) visible; prior buffers free
        if (i + 1 < NC) { load_w(i + 1, (i + 1) & 1); CP_COMMIT(); }

        // phase B(i)
        const float* vb = val_s + (i & 1) * KS * PX;
        const float* wb = w_s + (i & 1) * KS * O;
        #pragma unroll 4
        for (int kk = 0; kk < KS; kk++) {
            float4 v4 = *(const float4*)&vb[kk * PX + pg * 4];
            u64 vv[4];
            PACKDUP(vv[0], v4.x);
            PACKDUP(vv[1], v4.y);
            PACKDUP(vv[2], v4.z);
            PACKDUP(vv[3], v4.w);
            const ulonglong2* wp2 = (const ulonglong2*)&wb[kk * O + og * OT];
            #pragma unroll
            for (int q2 = 0; q2 < OT / 4; q2++) {
                ulonglong2 ww = wp2[q2];
                #pragma unroll
                for (int p = 0; p < 4; p++)
                    FMA2(acc[2 * q2][p], ww.x, vv[p], acc[2 * q2][p]);
                #pragma unroll
                for (int p = 0; p < 4; p++)
                    FMA2(acc[2 * q2 + 1][p], ww.y, vv[p], acc[2 * q2 + 1][p]);
            }
        }

        // phase A(i+1)
        if (i + 1 < NC) phaseA(i + 1, (i + 1) & 1);
    }

    const int gx = x0 + pg * 4;
    #pragma unroll
    for (int q = 0; q < OT / 2; q++) {
        float lo[4], hi[4];
        #pragma unroll
        for (int p = 0; p < 4; p++) {
            unsigned int ul, uh;
            UNPACK2(ul, uh, acc[q][p]);
            lo[p] = __uint_as_float(ul);
            hi[p] = __uint_as_float(uh);
        }
        #pragma unroll
        for (int h = 0; h < 2; h++) {
            int o = og * OT + 2 * q + h;
            float bvv = bias[o];
            const float* s = h ? hi : lo;
            float4 r4;
            r4.x = lrelu(s[0] + bvv);
            r4.y = lrelu(s[1] + bvv);
            r4.z = lrelu(s[2] + bvv);
            r4.w = lrelu(s[3] + bvv);
            *(float4*)&y[((b * O + o) * HH + yy) * WW + gx] = r4;
        }
    }
}

// ---------------------------------------------------------------------------
// Launch: one prep kernel (all 9 weight transposes), then 3 stages of
// conv(+leaky) -> offset conv -> deform conv(+leaky). Graph-capturable.
// ---------------------------------------------------------------------------
extern "C" void kernel_launch(void* const* d_in, const int* in_sizes, int n_in,
                              void* d_out, int out_size)
{
    const float* x = (const float*)d_in[0];
    const float* p[18];
    for (int i = 0; i < 18; i++) p[i] = (const float*)d_in[1 + i];

    float *A, *Bf, *OFF;
    float (*WTC)[128 * 9 * 128], (*WTO)[128 * 9 * 24], (*WTD)[128 * 9 * 128];
    cudaGetSymbolAddress((void**)&A,   g_A);
    cudaGetSymbolAddress((void**)&Bf,  g_B);
    cudaGetSymbolAddress((void**)&OFF, g_off);
    cudaGetSymbolAddress((void**)&WTC, g_wtc);
    cudaGetSymbolAddress((void**)&WTO, g_wto);
    cudaGetSymbolAddress((void**)&WTD, g_wtd);

    // ---- prep: all weight transposes in one launch ----
    PrepJobs jobs;
    const int cin_s[3]  = {64, 128, 128};   // conv cin per stage
    const int cout_s[3] = {128, 128, 64};   // conv cout / deform C=O per stage
    for (int s = 0; s < 3; s++) {
        jobs.src[3 * s + 0] = p[6 * s + 0];          // conv w
        jobs.dst[3 * s + 0] = WTC[s];
        jobs.C9[3 * s + 0] = cin_s[s] * 9;
        jobs.O[3 * s + 0] = cout_s[s];
        jobs.OP[3 * s + 0] = cout_s[s];
        jobs.src[3 * s + 1] = p[6 * s + 2];          // offset w
        jobs.dst[3 * s + 1] = WTO[s];
        jobs.C9[3 * s + 1] = cout_s[s] * 9;
        jobs.O[3 * s + 1] = 18;
        jobs.OP[3 * s + 1] = 24;
        jobs.src[3 * s + 2] = p[6 * s + 4];          // deform w
        jobs.dst[3 * s + 2] = WTD[s];
        jobs.C9[3 * s + 2] = cout_s[s] * 9;
        jobs.O[3 * s + 2] = cout_s[s];
        jobs.OP[3 * s + 2] = cout_s[s];
    }
    prep_kernel<<<dim3(64, 9), 256>>>(jobs);

    const int smemD128 = (2304 + 2 * 36 * 64 + 2 * 36 * 128) * 4;  // 64512
    const int smemD64  = (2304 + 2 * 36 * 64 + 2 * 36 * 64) * 4;   // 46080
    cudaFuncSetAttribute(dconv3x3_kernel<128, 128>,
                         cudaFuncAttributeMaxDynamicSharedMemorySize, smemD128);
    cudaFuncSetAttribute(dconv3x3_kernel<64, 64>,
                         cudaFuncAttributeMaxDynamicSharedMemorySize, smemD64);

    dim3 blk128(128), blk256(256);
    dim3 dgrid(WW / 64, HH, BB);

    // ---- stage 1: 64 -> 128 ----
    conv3x3_kernel<64, 16, true><<<dim3(4, 8, BB * 8), blk128>>>(x, WTC[0], p[1], A, 128, 128, 8);
    conv3x3_kernel<128, 8, false><<<dim3(4, 8, BB * 3), blk128>>>(A, WTO[0], p[3], OFF, 18, 24, 3);
    dconv3x3_kernel<128, 128><<<dgrid, blk256, smemD128>>>(A, OFF, WTD[0], p[5], Bf);

    // ---- stage 2: 128 -> 128 ----
    conv3x3_kernel<128, 16, true><<<dim3(4, 8, BB * 8), blk128>>>(Bf, WTC[1], p[7], A, 128, 128, 8);
    conv3x3_kernel<128, 8, false><<<dim3(4, 8, BB * 3), blk128>>>(A, WTO[1], p[9], OFF, 18, 24, 3);
    dconv3x3_kernel<128, 128><<<dgrid, blk256, smemD128>>>(A, OFF, WTD[1], p[11], Bf);

    // ---- stage 3: 128 -> 64 ----
    conv3x3_kernel<128, 16, true><<<dim3(4, 8, BB * 4), blk128>>>(Bf, WTC[2], p[13], A, 64, 64, 4);
    conv3x3_kernel<64, 8, false><<<dim3(4, 8, BB * 3), blk128>>>(A, WTO[2], p[15], OFF, 18, 24, 3);
    dconv3x3_kernel<64, 64><<<dgrid, blk256, smemD64>>>(A, OFF, WTD[2], p[17], (float*)d_out);
}

// round 8
// speedup vs baseline: 1.6837x; 1.1733x over previous
#include <cuda_runtime.h>
#include <math.h>

// Problem constants (fixed by reference: x = (4, 64, 128, 128) fp32)
#define HH 128
#define WW 128
#define BB 4

// Scratch (allocation-free: __device__ globals)
__device__ float g_A[BB * 128 * HH * WW];        // 32 MB ping
__device__ float g_B[BB * 128 * HH * WW];        // 32 MB pong
__device__ float g_off[BB * 18 * HH * WW];       // offsets
__device__ float g_wtc[3][128 * 9 * 128];        // per-stage transposed conv weights
__device__ float g_wto[3][128 * 9 * 24];         // per-stage transposed offset weights
__device__ float g_wtd[3][128 * 9 * 128];        // per-stage transposed deform weights

typedef unsigned long long u64;

// Packed fp32x2 ops (Blackwell FFMA2 — only reachable via PTX)
#define FMA2(d, a, b, c) \
    asm("fma.rn.f32x2 %0, %1, %2, %3;" : "=l"(d) : "l"(a), "l"(b), "l"(c))
#define PACKDUP(out, f) \
    asm("mov.b64 %0, {%1, %1};" : "=l"(out) : "r"(__float_as_uint(f)))
#define UNPACK2(lo, hi, in) \
    asm("mov.b64 {%0, %1}, %2;" : "=r"(lo), "=r"(hi) : "l"(in))

// cp.async (LDGSTS)
#define CP_ASYNC4(dst_s, src_g, szr) \
    asm volatile("cp.async.ca.shared.global [%0], [%1], 4, %2;" \
                 :: "r"(dst_s), "l"(src_g), "r"(szr))
#define CP_ASYNC16(dst_s, src_g) \
    asm volatile("cp.async.ca.shared.global [%0], [%1], 16;" \
                 :: "r"(dst_s), "l"(src_g))
#define CP_COMMIT() asm volatile("cp.async.commit_group;")
#define CP_WAIT0()  asm volatile("cp.async.wait_group 0;")

__device__ __forceinline__ unsigned s2u(const void* p) {
    return (unsigned)__cvta_generic_to_shared(p);
}
__device__ __forceinline__ float lrelu(float v) { return v >= 0.f ? v : 0.2f * v; }

// ---------------------------------------------------------------------------
// One prep kernel does ALL 9 weight transposes (they depend only on inputs).
// ---------------------------------------------------------------------------
struct PrepJobs {
    const float* src[9];
    float*       dst[9];
    int C9[9], O[9], OP[9];
};

__global__ void prep_kernel(PrepJobs jobs)
{
    int job = blockIdx.y;
    int C9 = jobs.C9[job], O = jobs.O[job], OP = jobs.OP[job];
    int n = C9 * OP;
    const float* src = jobs.src[job];
    float* dst = jobs.dst[job];
    for (int idx = blockIdx.x * 256 + threadIdx.x; idx < n; idx += gridDim.x * 256) {
        int j = idx / OP;
        int o = idx - j * OP;
        dst[idx] = (o < O) ? src[o * C9 + j] : 0.f;
    }
}

// ---------------------------------------------------------------------------
// Plain 3x3 conv (measured-best R4 form), stride 1, pad 1, optional LeakyReLU.
// 32(x) x 16(y) px tile, OCB oc per block, 128 threads.
// Thread: 4 px x OCB oc as OCB/2 f32x2 pairs.
// cp.async double-buffered input halo + weight slab, 1 barrier per chunk.
// ---------------------------------------------------------------------------
template<int CIN, int OCB, bool RELU>
__global__ __launch_bounds__(128)
void conv3x3_kernel(const float* __restrict__ x, const float* __restrict__ wt,
                    const float* __restrict__ bias, float* __restrict__ y,
                    int Cout, int OP, int n_ocb)
{
    __shared__ float w_s[2][36][OCB];
    __shared__ float in_s[2][4][18][34];

    const int t   = threadIdx.x;
    const int lx  = t & 7;
    const int ly  = t >> 3;
    const int bx  = blockIdx.x * 32;
    const int by  = blockIdx.y * 16;
    const int b   = blockIdx.z / n_ocb;
    const int ocb = blockIdx.z % n_ocb;
    const int oc0 = ocb * OCB;

    const float* xb = x + b * CIN * HH * WW;

    u64 acc[OCB / 2][4];
    #pragma unroll
    for (int q = 0; q < OCB / 2; q++)
        #pragma unroll
        for (int p = 0; p < 4; p++) acc[q][p] = 0ull;

    auto load_chunk = [&](int c0, int bi) {
        const float* xc = xb + c0 * HH * WW;
        unsigned in_base = s2u(&in_s[bi][0][0][0]);
        for (int i = t; i < 4 * 18 * 34; i += 128) {
            int cc  = i / (18 * 34);
            int rem = i - cc * (18 * 34);
            int r   = rem / 34;
            int col = rem - r * 34;
            int gy  = by - 1 + r;
            int gx  = bx - 1 + col;
            bool ok = ((unsigned)gy < (unsigned)HH) & ((unsigned)gx < (unsigned)WW);
            const float* src = xc + cc * HH * WW + (ok ? gy * WW + gx : 0);
            int sz = ok ? 4 : 0;
            CP_ASYNC4(in_base + i * 4, src, sz);
        }
        for (int i = t; i < 36 * (OCB / 4); i += 128) {
            int row = i / (OCB / 4);
            int q   = i - row * (OCB / 4);
            CP_ASYNC16(s2u(&w_s[bi][row][q * 4]),
                       &wt[(c0 * 9 + row) * OP + oc0 + q * 4]);
        }
    };

    load_chunk(0, 0);
    CP_COMMIT();

    int buf = 0;
    for (int c0 = 0; c0 < CIN; c0 += 4) {
        CP_WAIT0();
        __syncthreads();
        if (c0 + 4 < CIN) { load_chunk(c0 + 4, buf ^ 1); CP_COMMIT(); }

        #pragma unroll
        for (int cc = 0; cc < 4; cc++) {
            #pragma unroll
            for (int ry = 0; ry < 3; ry++) {
                float rowv[6];
                #pragma unroll
                for (int cl = 0; cl < 6; cl++)
                    rowv[cl] = in_s[buf][cc][ly + ry][lx * 4 + cl];
                #pragma unroll
                for (int rx = 0; rx < 3; rx++) {
                    u64 iv2[4];
                    #pragma unroll
                    for (int p = 0; p < 4; p++) PACKDUP(iv2[p], rowv[p + rx]);
                    const u64* wp = (const u64*)&w_s[buf][cc * 9 + ry * 3 + rx][0];
                    #pragma unroll
                    for (int q = 0; q < OCB / 2; q++) {
                        u64 w2 = wp[q];
                        #pragma unroll
                        for (int p = 0; p < 4; p++)
                            FMA2(acc[q][p], w2, iv2[p], acc[q][p]);
                    }
                }
            }
        }
        buf ^= 1;
    }

    const int gy = by + ly;
    const int gx = bx + lx * 4;
    #pragma unroll
    for (int q = 0; q < OCB / 2; q++) {
        float lo[4], hi[4];
        #pragma unroll
        for (int p = 0; p < 4; p++) {
            unsigned int ul, uh;
            UNPACK2(ul, uh, acc[q][p]);
            lo[p] = __uint_as_float(ul);
            hi[p] = __uint_as_float(uh);
        }
        #pragma unroll
        for (int h = 0; h < 2; h++) {
            int oc = 2 * q + h;
            if (oc0 + oc < Cout) {
                float bvv = bias[oc0 + oc];
                const float* s = h ? hi : lo;
                float v0 = s[0] + bvv, v1 = s[1] + bvv;
                float v2 = s[2] + bvv, v3 = s[3] + bvv;
                if (RELU) { v0 = lrelu(v0); v1 = lrelu(v1); v2 = lrelu(v2); v3 = lrelu(v3); }
                *(float4*)&y[((b * Cout + oc0 + oc) * HH + gy) * WW + gx] =
                    make_float4(v0, v1, v2, v3);
            }
        }
    }
}

// ---------------------------------------------------------------------------
// Deformable 3x3 conv + LeakyReLU.
// 256 threads, 64 px on one row, all O channels. CC=4 chunks,
// double-buffered val + weights (cp.async), one barrier per chunk.
// No taps smem: taps recomputed per chunk from offsets (L1-resident), and
// phase A handles all 4 channels per (k,px) with one address calc (MLP 16).
// smem 55.3KB (O=128) + regs<=64 -> 4 CTAs / 32 warps per SM.
// ---------------------------------------------------------------------------
template<int C, int O>
__global__ __launch_bounds__(256, 4)
void dconv3x3_kernel(const float* __restrict__ x, const float* __restrict__ off,
                     const float* __restrict__ wt, const float* __restrict__ bias,
                     float* __restrict__ y)
{
    constexpr int CC = 4;
    constexpr int PX = 64;
    constexpr int KS = CC * 9;          // 36
    constexpr int NC = C / CC;
    constexpr int OT = O / 16;          // 8 (O=128) or 4 (O=64)
    constexpr int HS = HH * WW;
    extern __shared__ __align__(16) float dsm[];
    float* val_s = dsm;                 // 2 * KS * PX
    float* w_s   = dsm + 2 * KS * PX;   // 2 * KS * O

    const int t  = threadIdx.x;
    const int og = t >> 4;               // 0..15
    const int pg = t & 15;               // 0..15 (px base = pg*4)
    const int x0 = blockIdx.x * PX;
    const int yy = blockIdx.y;
    const int b  = blockIdx.z;

    const float* xb  = x + b * C * HS;
    const float* ofb = off + (b * 18 * HH + yy) * WW + x0;

    auto load_w = [&](int ci, int bi) {
        const float4* src = (const float4*)(wt + ci * KS * O);
        float* dst = w_s + bi * KS * O;
        for (int i = t; i < KS * O / 4; i += 256)
            CP_ASYNC16(s2u(dst + i * 4), src + i);
    };

    // phase A: thread owns (k,px); recompute tap from offsets, gather all
    // CC channels with one address computation.
    auto phaseA = [&](int ci, int bi) {
        float* dst = val_s + bi * KS * PX;
        const float* xc = xb + ci * CC * HS;
        #pragma unroll 1
        for (int j = t; j < 9 * PX; j += 256) {
            int px = j & (PX - 1);
            int k  = j >> 6;
            float dy = ofb[(2 * k) * HS + px];
            float dx = ofb[(2 * k + 1) * HS + px];
            int ky = k / 3;
            int kx = k - ky * 3;
            float py  = (float)(yy + ky - 1) + dy;
            float pxx = (float)(x0 + px + kx - 1) + dx;
            float fy = floorf(py), fx = floorf(pxx);
            int yi = (int)fy, xi = (int)fx;
            float wyv = py - fy, wxv = pxx - fx;
            bool y0in = (unsigned)yi < (unsigned)HH;
            bool y1in = (unsigned)(yi + 1) < (unsigned)HH;
            bool x0in = (unsigned)xi < (unsigned)WW;
            bool x1in = (unsigned)(xi + 1) < (unsigned)WW;
            bool ok00 = y0in & x0in, ok01 = y0in & x1in;
            bool ok10 = y1in & x0in, ok11 = y1in & x1in;
            int base = yi * WW + xi;
            float a00[CC], a01[CC], a10[CC], a11[CC];
            #pragma unroll
            for (int cc = 0; cc < CC; cc++) {
                const float* p = xc + cc * HS + base;
                a00[cc] = ok00 ? p[0]      : 0.f;
                a01[cc] = ok01 ? p[1]      : 0.f;
                a10[cc] = ok10 ? p[WW]     : 0.f;
                a11[cc] = ok11 ? p[WW + 1] : 0.f;
            }
            float* d0 = dst + k * PX + px;
            #pragma unroll
            for (int cc = 0; cc < CC; cc++) {
                float v0 = a00[cc] + (a01[cc] - a00[cc]) * wxv;
                float v1 = a10[cc] + (a11[cc] - a10[cc]) * wxv;
                d0[cc * 9 * PX] = v0 + (v1 - v0) * wyv;
            }
        }
    };

    u64 acc[OT / 2][4];
    #pragma unroll
    for (int q = 0; q < OT / 2; q++)
        #pragma unroll
        for (int p = 0; p < 4; p++) acc[q][p] = 0ull;

    // prologue
    load_w(0, 0);
    CP_COMMIT();
    phaseA(0, 0);

    for (int i = 0; i < NC; i++) {
        CP_WAIT0();
        __syncthreads();      // val(i), w(i) visible; prior buffers free
        if (i + 1 < NC) { load_w(i + 1, (i + 1) & 1); CP_COMMIT(); }

        // phase B(i)
        const float* vb = val_s + (i & 1) * KS * PX;
        const float* wb = w_s + (i & 1) * KS * O;
        #pragma unroll 4
        for (int kk = 0; kk < KS; kk++) {
            float4 v4 = *(const float4*)&vb[kk * PX + pg * 4];
            u64 vv[4];
            PACKDUP(vv[0], v4.x);
            PACKDUP(vv[1], v4.y);
            PACKDUP(vv[2], v4.z);
            PACKDUP(vv[3], v4.w);
            const ulonglong2* wp2 = (const ulonglong2*)&wb[kk * O + og * OT];
            #pragma unroll
            for (int q2 = 0; q2 < OT / 4; q2++) {
                ulonglong2 ww = wp2[q2];
                #pragma unroll
                for (int p = 0; p < 4; p++)
                    FMA2(acc[2 * q2][p], ww.x, vv[p], acc[2 * q2][p]);
                #pragma unroll
                for (int p = 0; p < 4; p++)
                    FMA2(acc[2 * q2 + 1][p], ww.y, vv[p], acc[2 * q2 + 1][p]);
            }
        }

        // phase A(i+1)
        if (i + 1 < NC) phaseA(i + 1, (i + 1) & 1);
    }

    const int gx = x0 + pg * 4;
    #pragma unroll
    for (int q = 0; q < OT / 2; q++) {
        float lo[4], hi[4];
        #pragma unroll
        for (int p = 0; p < 4; p++) {
            unsigned int ul, uh;
            UNPACK2(ul, uh, acc[q][p]);
            lo[p] = __uint_as_float(ul);
            hi[p] = __uint_as_float(uh);
        }
        #pragma unroll
        for (int h = 0; h < 2; h++) {
            int o = og * OT + 2 * q + h;
            float bvv = bias[o];
            const float* s = h ? hi : lo;
            float4 r4;
            r4.x = lrelu(s[0] + bvv);
            r4.y = lrelu(s[1] + bvv);
            r4.z = lrelu(s[2] + bvv);
            r4.w = lrelu(s[3] + bvv);
            *(float4*)&y[((b * O + o) * HH + yy) * WW + gx] = r4;
        }
    }
}

// ---------------------------------------------------------------------------
// Launch: one prep kernel (all 9 weight transposes), then 3 stages of
// conv(+leaky) -> offset conv -> deform conv(+leaky). Graph-capturable.
// ---------------------------------------------------------------------------
extern "C" void kernel_launch(void* const* d_in, const int* in_sizes, int n_in,
                              void* d_out, int out_size)
{
    const float* x = (const float*)d_in[0];
    const float* p[18];
    for (int i = 0; i < 18; i++) p[i] = (const float*)d_in[1 + i];

    float *A, *Bf, *OFF;
    float (*WTC)[128 * 9 * 128], (*WTO)[128 * 9 * 24], (*WTD)[128 * 9 * 128];
    cudaGetSymbolAddress((void**)&A,   g_A);
    cudaGetSymbolAddress((void**)&Bf,  g_B);
    cudaGetSymbolAddress((void**)&OFF, g_off);
    cudaGetSymbolAddress((void**)&WTC, g_wtc);
    cudaGetSymbolAddress((void**)&WTO, g_wto);
    cudaGetSymbolAddress((void**)&WTD, g_wtd);

    // ---- prep: all weight transposes in one launch ----
    PrepJobs jobs;
    const int cin_s[3]  = {64, 128, 128};
    const int cout_s[3] = {128, 128, 64};
    for (int s = 0; s < 3; s++) {
        jobs.src[3 * s + 0] = p[6 * s + 0];
        jobs.dst[3 * s + 0] = WTC[s];
        jobs.C9[3 * s + 0] = cin_s[s] * 9;
        jobs.O[3 * s + 0] = cout_s[s];
        jobs.OP[3 * s + 0] = cout_s[s];
        jobs.src[3 * s + 1] = p[6 * s + 2];
        jobs.dst[3 * s + 1] = WTO[s];
        jobs.C9[3 * s + 1] = cout_s[s] * 9;
        jobs.O[3 * s + 1] = 18;
        jobs.OP[3 * s + 1] = 24;
        jobs.src[3 * s + 2] = p[6 * s + 4];
        jobs.dst[3 * s + 2] = WTD[s];
        jobs.C9[3 * s + 2] = cout_s[s] * 9;
        jobs.O[3 * s + 2] = cout_s[s];
        jobs.OP[3 * s + 2] = cout_s[s];
    }
    prep_kernel<<<dim3(64, 9), 256>>>(jobs);

    // dconv smem: val(2*36*64) + w(2*36*O) floats
    const int smemD128 = (2 * 36 * 64 + 2 * 36 * 128) * 4;  // 55296
    const int smemD64  = (2 * 36 * 64 + 2 * 36 * 64) * 4;   // 36864
    cudaFuncSetAttribute(dconv3x3_kernel<128, 128>,
                         cudaFuncAttributeMaxDynamicSharedMemorySize, smemD128);
    cudaFuncSetAttribute(dconv3x3_kernel<64, 64>,
                         cudaFuncAttributeMaxDynamicSharedMemorySize, smemD64);

    dim3 blk128(128), blk256(256);
    dim3 dgrid(WW / 64, HH, BB);

    // ---- stage 1: 64 -> 128 ----
    conv3x3_kernel<64, 16, true><<<dim3(4, 8, BB * 8), blk128>>>(x, WTC[0], p[1], A, 128, 128, 8);
    conv3x3_kernel<128, 8, false><<<dim3(4, 8, BB * 3), blk128>>>(A, WTO[0], p[3], OFF, 18, 24, 3);
    dconv3x3_kernel<128, 128><<<dgrid, blk256, smemD128>>>(A, OFF, WTD[0], p[5], Bf);

    // ---- stage 2: 128 -> 128 ----
    conv3x3_kernel<128, 16, true><<<dim3(4, 8, BB * 8), blk128>>>(Bf, WTC[1], p[7], A, 128, 128, 8);
    conv3x3_kernel<128, 8, false><<<dim3(4, 8, BB * 3), blk128>>>(A, WTO[1], p[9], OFF, 18, 24, 3);
    dconv3x3_kernel<128, 128><<<dgrid, blk256, smemD128>>>(A, OFF, WTD[1], p[11], Bf);

    // ---- stage 3: 128 -> 64 ----
    conv3x3_kernel<128, 16, true><<<dim3(4, 8, BB * 4), blk128>>>(Bf, WTC[2], p[13], A, 64, 64, 4);
    conv3x3_kernel<64, 8, false><<<dim3(4, 8, BB * 3), blk128>>>(A, WTO[2], p[15], OFF, 18, 24, 3);
    dconv3x3_kernel<64, 64><<<dgrid, blk256, smemD64>>>(A, OFF, WTD[2], p[17], (float*)d_out);
}

// round 9
// speedup vs baseline: 1.7713x; 1.0520x over previous
#include <cuda_runtime.h>
#include <math.h>

// Problem constants (fixed by reference: x = (4, 64, 128, 128) fp32)
#define HH 128
#define WW 128
#define BB 4

// Scratch (allocation-free: __device__ globals)
__device__ float g_A[BB * 128 * HH * WW];        // 32 MB ping
__device__ float g_B[BB * 128 * HH * WW];        // 32 MB pong
__device__ float g_off[BB * 18 * HH * WW];       // offsets
__device__ float g_wtc[3][128 * 9 * 128];        // per-stage transposed conv weights
__device__ float g_wto[3][128 * 9 * 24];         // per-stage transposed offset weights
__device__ float g_wtd[3][128 * 9 * 128];        // per-stage transposed deform weights

typedef unsigned long long u64;

// Packed fp32x2 ops (Blackwell FFMA2 — only reachable via PTX)
#define FMA2(d, a, b, c) \
    asm("fma.rn.f32x2 %0, %1, %2, %3;" : "=l"(d) : "l"(a), "l"(b), "l"(c))
#define PACKDUP(out, f) \
    asm("mov.b64 %0, {%1, %1};" : "=l"(out) : "r"(__float_as_uint(f)))
#define UNPACK2(lo, hi, in) \
    asm("mov.b64 {%0, %1}, %2;" : "=r"(lo), "=r"(hi) : "l"(in))

// cp.async (LDGSTS)
#define CP_ASYNC4(dst_s, src_g, szr) \
    asm volatile("cp.async.ca.shared.global [%0], [%1], 4, %2;" \
                 :: "r"(dst_s), "l"(src_g), "r"(szr))
#define CP_ASYNC16(dst_s, src_g) \
    asm volatile("cp.async.ca.shared.global [%0], [%1], 16;" \
                 :: "r"(dst_s), "l"(src_g))
#define CP_ASYNC16Z(dst_s, src_g, szr) \
    asm volatile("cp.async.ca.shared.global [%0], [%1], 16, %2;" \
                 :: "r"(dst_s), "l"(src_g), "r"(szr))
#define CP_COMMIT() asm volatile("cp.async.commit_group;")
#define CP_WAIT0()  asm volatile("cp.async.wait_group 0;")

__device__ __forceinline__ unsigned s2u(const void* p) {
    return (unsigned)__cvta_generic_to_shared(p);
}
__device__ __forceinline__ float lrelu(float v) { return v >= 0.f ? v : 0.2f * v; }

// ---------------------------------------------------------------------------
// One prep kernel does ALL 9 weight transposes (they depend only on inputs).
// ---------------------------------------------------------------------------
struct PrepJobs {
    const float* src[9];
    float*       dst[9];
    int C9[9], O[9], OP[9];
};

__global__ void prep_kernel(PrepJobs jobs)
{
    int job = blockIdx.y;
    int C9 = jobs.C9[job], O = jobs.O[job], OP = jobs.OP[job];
    int n = C9 * OP;
    const float* src = jobs.src[job];
    float* dst = jobs.dst[job];
    for (int idx = blockIdx.x * 256 + threadIdx.x; idx < n; idx += gridDim.x * 256) {
        int j = idx / OP;
        int o = idx - j * OP;
        dst[idx] = (o < O) ? src[o * C9 + j] : 0.f;
    }
}

// ---------------------------------------------------------------------------
// Plain 3x3 conv, stride 1, pad 1, optional LeakyReLU.
// 32(x) x 16(y) px tile, OCB oc per block, 128 threads, 5 CTAs/SM (reg cap).
// Thread: 4 px x OCB oc as OCB/2 f32x2 pairs.
// cp.async double-buffered: interior columns via 16B copies (gmem-aligned),
// 1-px edges via 4B copies. Rows padded to 40 floats so the interior slot
// (col 4) stays 16B-aligned on every row. 1 barrier per chunk.
// ---------------------------------------------------------------------------
template<int CIN, int OCB, bool RELU>
__global__ __launch_bounds__(128, 5)
void conv3x3_kernel(const float* __restrict__ x, const float* __restrict__ wt,
                    const float* __restrict__ bias, float* __restrict__ y,
                    int Cout, int OP, int n_ocb)
{
    __shared__ float w_s[2][36][OCB];
    __shared__ __align__(16) float in_s[2][4][18][40];
    // layout per row: col 3 = gx bx-1, cols 4..35 = bx..bx+31, col 36 = bx+32

    const int t   = threadIdx.x;
    const int lx  = t & 7;
    const int ly  = t >> 3;
    const int bx  = blockIdx.x * 32;
    const int by  = blockIdx.y * 16;
    const int b   = blockIdx.z / n_ocb;
    const int ocb = blockIdx.z % n_ocb;
    const int oc0 = ocb * OCB;

    const float* xb = x + b * CIN * HH * WW;

    u64 acc[OCB / 2][4];
    #pragma unroll
    for (int q = 0; q < OCB / 2; q++)
        #pragma unroll
        for (int p = 0; p < 4; p++) acc[q][p] = 0ull;

    auto load_chunk = [&](int c0, int bi) {
        const float* xc = xb + c0 * HH * WW;
        // interior: 4cc x 18r x 8 float4 (gmem 16B-aligned: bx % 32 == 0)
        for (int i = t; i < 4 * 18 * 8; i += 128) {
            int cc  = i / 144;
            int rem = i - cc * 144;
            int r   = rem >> 3;
            int q   = rem & 7;
            int gy  = by - 1 + r;
            bool ok = (unsigned)gy < (unsigned)HH;
            const float* src = xc + cc * HH * WW + (ok ? gy * WW + bx + q * 4 : 0);
            int sz = ok ? 16 : 0;
            CP_ASYNC16Z(s2u(&in_s[bi][cc][r][4 + q * 4]), src, sz);
        }
        // edges: 4cc x 18r x 2
        for (int i = t; i < 4 * 18 * 2; i += 128) {
            int cc   = i / 36;
            int rem  = i - cc * 36;
            int r    = rem >> 1;
            int side = rem & 1;
            int gy   = by - 1 + r;
            int gx   = side ? bx + 32 : bx - 1;
            bool ok  = ((unsigned)gy < (unsigned)HH) & ((unsigned)gx < (unsigned)WW);
            const float* src = xc + cc * HH * WW + (ok ? gy * WW + gx : 0);
            int sz = ok ? 4 : 0;
            CP_ASYNC4(s2u(&in_s[bi][cc][r][side ? 36 : 3]), src, sz);
        }
        // weights
        for (int i = t; i < 36 * (OCB / 4); i += 128) {
            int row = i / (OCB / 4);
            int q   = i - row * (OCB / 4);
            CP_ASYNC16(s2u(&w_s[bi][row][q * 4]),
                       &wt[(c0 * 9 + row) * OP + oc0 + q * 4]);
        }
    };

    load_chunk(0, 0);
    CP_COMMIT();

    int buf = 0;
    for (int c0 = 0; c0 < CIN; c0 += 4) {
        CP_WAIT0();
        __syncthreads();
        if (c0 + 4 < CIN) { load_chunk(c0 + 4, buf ^ 1); CP_COMMIT(); }

        #pragma unroll
        for (int cc = 0; cc < 4; cc++) {
            #pragma unroll
            for (int ry = 0; ry < 3; ry++) {
                float rowv[6];
                #pragma unroll
                for (int cl = 0; cl < 6; cl++)
                    rowv[cl] = in_s[buf][cc][ly + ry][lx * 4 + 3 + cl];
                #pragma unroll
                for (int rx = 0; rx < 3; rx++) {
                    u64 iv2[4];
                    #pragma unroll
                    for (int p = 0; p < 4; p++) PACKDUP(iv2[p], rowv[p + rx]);
                    const u64* wp = (const u64*)&w_s[buf][cc * 9 + ry * 3 + rx][0];
                    #pragma unroll
                    for (int q = 0; q < OCB / 2; q++) {
                        u64 w2 = wp[q];
                        #pragma unroll
                        for (int p = 0; p < 4; p++)
                            FMA2(acc[q][p], w2, iv2[p], acc[q][p]);
                    }
                }
            }
        }
        buf ^= 1;
    }

    const int gy = by + ly;
    const int gx = bx + lx * 4;
    #pragma unroll
    for (int q = 0; q < OCB / 2; q++) {
        float lo[4], hi[4];
        #pragma unroll
        for (int p = 0; p < 4; p++) {
            unsigned int ul, uh;
            UNPACK2(ul, uh, acc[q][p]);
            lo[p] = __uint_as_float(ul);
            hi[p] = __uint_as_float(uh);
        }
        #pragma unroll
        for (int h = 0; h < 2; h++) {
            int oc = 2 * q + h;
            if (oc0 + oc < Cout) {
                float bvv = bias[oc0 + oc];
                const float* s = h ? hi : lo;
                float v0 = s[0] + bvv, v1 = s[1] + bvv;
                float v2 = s[2] + bvv, v3 = s[3] + bvv;
                if (RELU) { v0 = lrelu(v0); v1 = lrelu(v1); v2 = lrelu(v2); v3 = lrelu(v3); }
                *(float4*)&y[((b * Cout + oc0 + oc) * HH + gy) * WW + gx] =
                    make_float4(v0, v1, v2, v3);
            }
        }
    }
}

// ---------------------------------------------------------------------------
// Deformable 3x3 conv + LeakyReLU (R7 measured-best form — untouched).
// 256 threads, 64 px on one row, all O channels. CC=4 chunks,
// double-buffered val + weights (cp.async), one barrier per chunk.
// Taps recomputed per chunk from offsets; phase A gathers all 4 channels
// per (k,px) with one address calc. smem 55.3KB + regs<=64 -> 4 CTAs/SM.
// ---------------------------------------------------------------------------
template<int C, int O>
__global__ __launch_bounds__(256, 4)
void dconv3x3_kernel(const float* __restrict__ x, const float* __restrict__ off,
                     const float* __restrict__ wt, const float* __restrict__ bias,
                     float* __restrict__ y)
{
    constexpr int CC = 4;
    constexpr int PX = 64;
    constexpr int KS = CC * 9;          // 36
    constexpr int NC = C / CC;
    constexpr int OT = O / 16;          // 8 (O=128) or 4 (O=64)
    constexpr int HS = HH * WW;
    extern __shared__ __align__(16) float dsm[];
    float* val_s = dsm;                 // 2 * KS * PX
    float* w_s   = dsm + 2 * KS * PX;   // 2 * KS * O

    const int t  = threadIdx.x;
    const int og = t >> 4;               // 0..15
    const int pg = t & 15;               // 0..15 (px base = pg*4)
    const int x0 = blockIdx.x * PX;
    const int yy = blockIdx.y;
    const int b  = blockIdx.z;

    const float* xb  = x + b * C * HS;
    const float* ofb = off + (b * 18 * HH + yy) * WW + x0;

    auto load_w = [&](int ci, int bi) {
        const float4* src = (const float4*)(wt + ci * KS * O);
        float* dst = w_s + bi * KS * O;
        for (int i = t; i < KS * O / 4; i += 256)
            CP_ASYNC16(s2u(dst + i * 4), src + i);
    };

    auto phaseA = [&](int ci, int bi) {
        float* dst = val_s + bi * KS * PX;
        const float* xc = xb + ci * CC * HS;
        #pragma unroll 1
        for (int j = t; j < 9 * PX; j += 256) {
            int px = j & (PX - 1);
            int k  = j >> 6;
            float dy = ofb[(2 * k) * HS + px];
            float dx = ofb[(2 * k + 1) * HS + px];
            int ky = k / 3;
            int kx = k - ky * 3;
            float py  = (float)(yy + ky - 1) + dy;
            float pxx = (float)(x0 + px + kx - 1) + dx;
            float fy = floorf(py), fx = floorf(pxx);
            int yi = (int)fy, xi = (int)fx;
            float wyv = py - fy, wxv = pxx - fx;
            bool y0in = (unsigned)yi < (unsigned)HH;
            bool y1in = (unsigned)(yi + 1) < (unsigned)HH;
            bool x0in = (unsigned)xi < (unsigned)WW;
            bool x1in = (unsigned)(xi + 1) < (unsigned)WW;
            bool ok00 = y0in & x0in, ok01 = y0in & x1in;
            bool ok10 = y1in & x0in, ok11 = y1in & x1in;
            int base = yi * WW + xi;
            float a00[CC], a01[CC], a10[CC], a11[CC];
            #pragma unroll
            for (int cc = 0; cc < CC; cc++) {
                const float* p = xc + cc * HS + base;
                a00[cc] = ok00 ? p[0]      : 0.f;
                a01[cc] = ok01 ? p[1]      : 0.f;
                a10[cc] = ok10 ? p[WW]     : 0.f;
                a11[cc] = ok11 ? p[WW + 1] : 0.f;
            }
            float* d0 = dst + k * PX + px;
            #pragma unroll
            for (int cc = 0; cc < CC; cc++) {
                float v0 = a00[cc] + (a01[cc] - a00[cc]) * wxv;
                float v1 = a10[cc] + (a11[cc] - a10[cc]) * wxv;
                d0[cc * 9 * PX] = v0 + (v1 - v0) * wyv;
            }
        }
    };

    u64 acc[OT / 2][4];
    #pragma unroll
    for (int q = 0; q < OT / 2; q++)
        #pragma unroll
        for (int p = 0; p < 4; p++) acc[q][p] = 0ull;

    // prologue
    load_w(0, 0);
    CP_COMMIT();
    phaseA(0, 0);

    for (int i = 0; i < NC; i++) {
        CP_WAIT0();
        __syncthreads();      // val(i), w(i) visible; prior buffers free
        if (i + 1 < NC) { load_w(i + 1, (i + 1) & 1); CP_COMMIT(); }

        // phase B(i)
        const float* vb = val_s + (i & 1) * KS * PX;
        const float* wb = w_s + (i & 1) * KS * O;
        #pragma unroll 4
        for (int kk = 0; kk < KS; kk++) {
            float4 v4 = *(const float4*)&vb[kk * PX + pg * 4];
            u64 vv[4];
            PACKDUP(vv[0], v4.x);
            PACKDUP(vv[1], v4.y);
            PACKDUP(vv[2], v4.z);
            PACKDUP(vv[3], v4.w);
            const ulonglong2* wp2 = (const ulonglong2*)&wb[kk * O + og * OT];
            #pragma unroll
            for (int q2 = 0; q2 < OT / 4; q2++) {
                ulonglong2 ww = wp2[q2];
                #pragma unroll
                for (int p = 0; p < 4; p++)
                    FMA2(acc[2 * q2][p], ww.x, vv[p], acc[2 * q2][p]);
                #pragma unroll
                for (int p = 0; p < 4; p++)
                    FMA2(acc[2 * q2 + 1][p], ww.y, vv[p], acc[2 * q2 + 1][p]);
            }
        }

        // phase A(i+1)
        if (i + 1 < NC) phaseA(i + 1, (i + 1) & 1);
    }

    const int gx = x0 + pg * 4;
    #pragma unroll
    for (int q = 0; q < OT / 2; q++) {
        float lo[4], hi[4];
        #pragma unroll
        for (int p = 0; p < 4; p++) {
            unsigned int ul, uh;
            UNPACK2(ul, uh, acc[q][p]);
            lo[p] = __uint_as_float(ul);
            hi[p] = __uint_as_float(uh);
        }
        #pragma unroll
        for (int h = 0; h < 2; h++) {
            int o = og * OT + 2 * q + h;
            float bvv = bias[o];
            const float* s = h ? hi : lo;
            float4 r4;
            r4.x = lrelu(s[0] + bvv);
            r4.y = lrelu(s[1] + bvv);
            r4.z = lrelu(s[2] + bvv);
            r4.w = lrelu(s[3] + bvv);
            *(float4*)&y[((b * O + o) * HH + yy) * WW + gx] = r4;
        }
    }
}

// ---------------------------------------------------------------------------
// Launch: one prep kernel (all 9 weight transposes), then 3 stages of
// conv(+leaky) -> offset conv -> deform conv(+leaky). Graph-capturable.
// ---------------------------------------------------------------------------
extern "C" void kernel_launch(void* const* d_in, const int* in_sizes, int n_in,
                              void* d_out, int out_size)
{
    const float* x = (const float*)d_in[0];
    const float* p[18];
    for (int i = 0; i < 18; i++) p[i] = (const float*)d_in[1 + i];

    float *A, *Bf, *OFF;
    float (*WTC)[128 * 9 * 128], (*WTO)[128 * 9 * 24], (*WTD)[128 * 9 * 128];
    cudaGetSymbolAddress((void**)&A,   g_A);
    cudaGetSymbolAddress((void**)&Bf,  g_B);
    cudaGetSymbolAddress((void**)&OFF, g_off);
    cudaGetSymbolAddress((void**)&WTC, g_wtc);
    cudaGetSymbolAddress((void**)&WTO, g_wto);
    cudaGetSymbolAddress((void**)&WTD, g_wtd);

    // ---- prep: all weight transposes in one launch ----
    PrepJobs jobs;
    const int cin_s[3]  = {64, 128, 128};
    const int cout_s[3] = {128, 128, 64};
    for (int s = 0; s < 3; s++) {
        jobs.src[3 * s + 0] = p[6 * s + 0];
        jobs.dst[3 * s + 0] = WTC[s];
        jobs.C9[3 * s + 0] = cin_s[s] * 9;
        jobs.O[3 * s + 0] = cout_s[s];
        jobs.OP[3 * s + 0] = cout_s[s];
        jobs.src[3 * s + 1] = p[6 * s + 2];
        jobs.dst[3 * s + 1] = WTO[s];
        jobs.C9[3 * s + 1] = cout_s[s] * 9;
        jobs.O[3 * s + 1] = 18;
        jobs.OP[3 * s + 1] = 24;
        jobs.src[3 * s + 2] = p[6 * s + 4];
        jobs.dst[3 * s + 2] = WTD[s];
        jobs.C9[3 * s + 2] = cout_s[s] * 9;
        jobs.O[3 * s + 2] = cout_s[s];
        jobs.OP[3 * s + 2] = cout_s[s];
    }
    prep_kernel<<<dim3(64, 9), 256>>>(jobs);

    // dconv smem: val(2*36*64) + w(2*36*O) floats
    const int smemD128 = (2 * 36 * 64 + 2 * 36 * 128) * 4;  // 55296
    const int smemD64  = (2 * 36 * 64 + 2 * 36 * 64) * 4;   // 36864
    cudaFuncSetAttribute(dconv3x3_kernel<128, 128>,
                         cudaFuncAttributeMaxDynamicSharedMemorySize, smemD128);
    cudaFuncSetAttribute(dconv3x3_kernel<64, 64>,
                         cudaFuncAttributeMaxDynamicSharedMemorySize, smemD64);

    dim3 blk128(128), blk256(256);
    dim3 dgrid(WW / 64, HH, BB);

    // ---- stage 1: 64 -> 128 ----
    conv3x3_kernel<64, 16, true><<<dim3(4, 8, BB * 8), blk128>>>(x, WTC[0], p[1], A, 128, 128, 8);
    conv3x3_kernel<128, 8, false><<<dim3(4, 8, BB * 3), blk128>>>(A, WTO[0], p[3], OFF, 18, 24, 3);
    dconv3x3_kernel<128, 128><<<dgrid, blk256, smemD128>>>(A, OFF, WTD[0], p[5], Bf);

    // ---- stage 2: 128 -> 128 ----
    conv3x3_kernel<128, 16, true><<<dim3(4, 8, BB * 8), blk128>>>(Bf, WTC[1], p[7], A, 128, 128, 8);
    conv3x3_kernel<128, 8, false><<<dim3(4, 8, BB * 3), blk128>>>(A, WTO[1], p[9], OFF, 18, 24, 3);
    dconv3x3_kernel<128, 128><<<dgrid, blk256, smemD128>>>(A, OFF, WTD[1], p[11], Bf);

    // ---- stage 3: 128 -> 64 ----
    conv3x3_kernel<128, 16, true><<<dim3(4, 8, BB * 4), blk128>>>(Bf, WTC[2], p[13], A, 64, 64, 4);
    conv3x3_kernel<64, 8, false><<<dim3(4, 8, BB * 3), blk128>>>(A, WTO[2], p[15], OFF, 18, 24, 3);
    dconv3x3_kernel<64, 64><<<dgrid, blk256, smemD64>>>(A, OFF, WTD[2], p[17], (float*)d_out);
}